// round 2
// baseline (speedup 1.0000x reference)
#include <cuda_runtime.h>

#define LENGTH   262144
#define NFFT     2048
#define HOP      512
#define BATCH    16
#define FRAMES   513        // (262144)/512 + 1 after reflect pad 1024/1024
#define KHALF    1025       // bins 0..1024 computed, rest mirrored
#define TILE_K   128        // k-bins per block
#define TILE_F   32         // frames per block
#define CHUNK    32         // n-samples per smem chunk

__global__ __launch_bounds__(256, 3) void dft_kernel(
    const float* __restrict__ x,
    const float* __restrict__ wsin,
    const float* __restrict__ wcos,
    float* __restrict__ out)
{
    __shared__ __align__(16) float sc[CHUNK][TILE_K];     // wcos tile, transposed [n][k]
    __shared__ __align__(16) float ss[CHUNK][TILE_K];     // wsin tile, transposed [n][k]
    __shared__ __align__(16) float sx[TILE_F][CHUNK + 1]; // frame samples [f][n]

    const int k0  = blockIdx.x * TILE_K;
    const int f0  = blockIdx.y * TILE_F;
    const int b   = blockIdx.z;
    const int tid = threadIdx.x;
    const int fcol = tid & 15;   // -> frames fcol*2, fcol*2+1
    const int krow = tid >> 4;   // -> k local krow*8 .. krow*8+7

    const float* __restrict__ xb = x + (size_t)b * LENGTH;

    float accC[8][2];
    float accS[8][2];
    #pragma unroll
    for (int i = 0; i < 8; i++) {
        accC[i][0] = 0.f; accC[i][1] = 0.f;
        accS[i][0] = 0.f; accS[i][1] = 0.f;
    }

    for (int n0 = 0; n0 < NFFT; n0 += CHUNK) {
        // ---- load W tiles (transpose [k][n] -> [n][k]) ----
        // 128 rows x 32 cols = 1024 float4 per matrix; 256 threads x 4
        #pragma unroll
        for (int r = 0; r < 4; r++) {
            int idx  = tid + r * 256;   // [0, 1024)
            int row  = idx >> 3;        // k local 0..127
            int col4 = idx & 7;         // n-group 0..7
            size_t g = (size_t)(k0 + row) * NFFT + n0 + col4 * 4;
            float4 c4 = *(const float4*)(wcos + g);
            float4 s4 = *(const float4*)(wsin + g);
            sc[col4*4+0][row] = c4.x; sc[col4*4+1][row] = c4.y;
            sc[col4*4+2][row] = c4.z; sc[col4*4+3][row] = c4.w;
            ss[col4*4+0][row] = s4.x; ss[col4*4+1][row] = s4.y;
            ss[col4*4+2][row] = s4.z; ss[col4*4+3][row] = s4.w;
        }
        // ---- load x tile with fused reflect padding ----
        // 32 frames x 32 samples = 1024 floats; 256 threads x 4
        #pragma unroll
        for (int r = 0; r < 4; r++) {
            int idx = tid + r * 256;    // [0, 1024)
            int f   = idx >> 5;         // 0..31
            int j   = idx & 31;         // 0..31
            long gi = (long)(f0 + f) * HOP + n0 + j - (NFFT / 2);
            if (gi < 0)        gi = -gi;
            if (gi >= LENGTH)  gi = 2L * LENGTH - 2 - gi;
            sx[f][j] = xb[gi];
        }
        __syncthreads();

        // ---- 32-step inner product ----
        #pragma unroll
        for (int j = 0; j < CHUNK; j++) {
            float x0 = sx[fcol*2 + 0][j];
            float x1 = sx[fcol*2 + 1][j];
            float4 c0 = *(const float4*)&sc[j][krow*8];
            float4 c1 = *(const float4*)&sc[j][krow*8 + 4];
            float4 s0 = *(const float4*)&ss[j][krow*8];
            float4 s1 = *(const float4*)&ss[j][krow*8 + 4];
            float cv[8] = {c0.x, c0.y, c0.z, c0.w, c1.x, c1.y, c1.z, c1.w};
            float sv[8] = {s0.x, s0.y, s0.z, s0.w, s1.x, s1.y, s1.z, s1.w};
            #pragma unroll
            for (int i = 0; i < 8; i++) {
                accC[i][0] = fmaf(cv[i], x0, accC[i][0]);
                accC[i][1] = fmaf(cv[i], x1, accC[i][1]);
                accS[i][0] = fmaf(sv[i], x0, accS[i][0]);
                accS[i][1] = fmaf(sv[i], x1, accS[i][1]);
            }
        }
        __syncthreads();
    }

    // ---- epilogue: write k and its mirror (2048-k) ----
    const size_t TOT = (size_t)BATCH * NFFT * FRAMES;
    #pragma unroll
    for (int i = 0; i < 8; i++) {
        int k = k0 + krow * 8 + i;
        if (k >= KHALF) continue;
        #pragma unroll
        for (int j = 0; j < 2; j++) {
            int t = f0 + fcol * 2 + j;
            if (t >= FRAMES) continue;
            size_t o = ((size_t)b * NFFT + k) * FRAMES + t;
            out[o]       = accC[i][j];   // real
            out[TOT + o] = -accS[i][j];  // -imag
            if (k >= 1 && k <= NFFT/2 - 1) {
                size_t om = ((size_t)b * NFFT + (NFFT - k)) * FRAMES + t;
                out[om]       = accC[i][j];  // real mirrored (cos symmetric)
                out[TOT + om] = accS[i][j];  // -imag mirrored (sin antisymmetric)
            }
        }
    }
}

extern "C" void kernel_launch(void* const* d_in, const int* in_sizes, int n_in,
                              void* d_out, int out_size) {
    const float* x    = (const float*)d_in[0];
    const float* wsin = (const float*)d_in[1];
    const float* wcos = (const float*)d_in[2];
    float* out = (float*)d_out;

    dim3 grid((KHALF + TILE_K - 1) / TILE_K,   // 9
              (FRAMES + TILE_F - 1) / TILE_F,  // 17
              BATCH);                          // 16
    dft_kernel<<<grid, 256>>>(x, wsin, wcos, out);
}

// round 4
// speedup vs baseline: 4.0664x; 4.0664x over previous
#include <cuda_runtime.h>
#include <cstdint>

#define LENGTH   262144
#define NFFT     2048
#define HOP      512
#define BATCH    16
#define FRAMES   513
#define NCOLS    (BATCH * FRAMES)      // 8208
#define NCOLS_PAD 8320                 // 65 * 128
#define KBINS    1024                  // bins 0..1023 via GEMM, 1024 via aux
#define MC       256                   // CTA rows: 128 cos + 128 sin
#define NC       128                   // CTA cols
#define KC       32                    // k-chunk (floats) = 128 bytes/row
#define NCHUNK   (NFFT / KC)           // 64
#define STAGES   3
#define A_BYTES  (MC * 128)            // 32768
#define B_BYTES  (NC * 128)            // 16384
#define STAGE_BYTES (A_BYTES + B_BYTES) // 49152
#define SMEM_TOTAL  (STAGES * STAGE_BYTES) // 147456

__device__ __align__(16) float g_wc[KBINS * NFFT];       // 8.4 MB
__device__ __align__(16) float g_ws[KBINS * NFFT];       // 8.4 MB
__device__ __align__(16) float g_B[NCOLS_PAD * NFFT];    // 68.2 MB

__device__ __forceinline__ uint32_t smem_u32(const void* p) {
    uint32_t a;
    asm("{ .reg .u64 t; cvta.to.shared.u64 t, %1; cvt.u32.u64 %0, t; }" : "=r"(a) : "l"(p));
    return a;
}

__device__ __forceinline__ float tf32r(float v) {
    uint32_t u;
    asm("cvt.rna.tf32.f32 %0, %1;" : "=r"(u) : "f"(v));
    return __uint_as_float(u);
}

__device__ __forceinline__ void cpa(uint32_t dst, uint64_t gsrc) {
    asm volatile("cp.async.cg.shared.global [%0], [%1], 16;" :: "r"(dst), "l"(gsrc) : "memory");
}

__device__ __forceinline__ void ldsm4(uint32_t* r, uint32_t a) {
    asm volatile("ldmatrix.sync.aligned.m8n8.x4.shared.b16 {%0,%1,%2,%3}, [%4];"
        : "=r"(r[0]), "=r"(r[1]), "=r"(r[2]), "=r"(r[3]) : "r"(a));
}

__device__ __forceinline__ void mma8(float* c, const uint32_t* a, const uint32_t* b) {
    asm volatile("mma.sync.aligned.m16n8k8.row.col.f32.tf32.tf32.f32 "
        "{%0,%1,%2,%3}, {%4,%5,%6,%7}, {%8,%9}, {%0,%1,%2,%3};"
        : "+f"(c[0]), "+f"(c[1]), "+f"(c[2]), "+f"(c[3])
        : "r"(a[0]), "r"(a[1]), "r"(a[2]), "r"(a[3]), "r"(b[0]), "r"(b[1]));
}

// ---------------- prep kernel 1: round W rows 0..1023 to tf32 ----------------
__global__ __launch_bounds__(256) void round_w(
    const float* __restrict__ wsin, const float* __restrict__ wcos)
{
    size_t i = (size_t)blockIdx.x * 256 + threadIdx.x;   // float4 index, < 524288
    float4 c = ((const float4*)wcos)[i];
    float4 s = ((const float4*)wsin)[i];
    c.x = tf32r(c.x); c.y = tf32r(c.y); c.z = tf32r(c.z); c.w = tf32r(c.w);
    s.x = tf32r(s.x); s.y = tf32r(s.y); s.z = tf32r(s.z); s.w = tf32r(s.w);
    ((float4*)g_wc)[i] = c;
    ((float4*)g_ws)[i] = s;
}

// ---------------- prep kernel 2: materialize frame matrix B ----------------
__global__ __launch_bounds__(256) void build_B(const float* __restrict__ x)
{
    int col = blockIdx.x;                  // 0..8319
    int tid = threadIdx.x;
    float4* dst = (float4*)(g_B + (size_t)col * NFFT);
    if (col >= NCOLS) {
        float4 z = make_float4(0.f, 0.f, 0.f, 0.f);
        dst[tid] = z; dst[tid + 256] = z;
        return;
    }
    int b = col / FRAMES;
    int t = col - b * FRAMES;
    const float* xb = x + (size_t)b * LENGTH;
    int base = t * HOP - (NFFT / 2);
    #pragma unroll
    for (int r = 0; r < 2; r++) {
        int n = (tid + r * 256) * 4;
        int gi = base + n;
        float4 v;
        if (gi >= 0 && gi + 3 < LENGTH) {
            v = *(const float4*)(xb + gi);
        } else {
            float tmp[4];
            #pragma unroll
            for (int e = 0; e < 4; e++) {
                int ii = gi + e;
                if (ii < 0) ii = -ii;
                else if (ii >= LENGTH) ii = 2 * LENGTH - 2 - ii;
                tmp[e] = xb[ii];
            }
            v = make_float4(tmp[0], tmp[1], tmp[2], tmp[3]);
        }
        v.x = tf32r(v.x); v.y = tf32r(v.y); v.z = tf32r(v.z); v.w = tf32r(v.w);
        dst[tid + r * 256] = v;
    }
}

// ---------------- main GEMM ----------------
__device__ __forceinline__ void compute_chunk(
    uint32_t st, float acc[8][4][4], int wm, int wn, int lane)
{
    const uint32_t aBase = st + wm * (128 * 128);   // cos rows 0..127 / sin rows 128..255
    const uint32_t bBase = st + A_BYTES;
    const int arow = lane & 15;
    const int ahi  = (lane >> 4) & 1;          // +16B within k-step
    const int bcol = wn * 32 + (lane & 7) + (((lane >> 4) & 1) << 3);
    const int bhi  = (lane >> 3) & 1;

    #pragma unroll
    for (int ks = 0; ks < 4; ks++) {
        uint32_t bf[2][4];
        #pragma unroll
        for (int nt2 = 0; nt2 < 2; nt2++) {
            int col = bcol + nt2 * 16;
            int kg = ks * 2 + bhi;
            uint32_t addr = bBase + col * 128 + (((kg ^ (col & 7))) << 4);
            ldsm4(bf[nt2], addr);
        }
        #pragma unroll
        for (int mt = 0; mt < 8; mt++) {
            int row = mt * 16 + arow;
            int kg = ks * 2 + ahi;
            uint32_t addr = aBase + row * 128 + (((kg ^ (row & 7))) << 4);
            uint32_t af[4];
            ldsm4(af, addr);
            #pragma unroll
            for (int nt = 0; nt < 4; nt++)
                mma8(acc[mt][nt], af, &bf[nt >> 1][(nt & 1) * 2]);
        }
    }
}

__global__ __launch_bounds__(256, 1) void stft_mma(float* __restrict__ out)
{
    extern __shared__ __align__(128) char smem[];
    const uint32_t sb = smem_u32(smem);
    const int tid = threadIdx.x;
    const int lane = tid & 31;
    const int wid = tid >> 5;
    const int ct = blockIdx.x;              // 0..64
    const int k0 = blockIdx.y * 128;        // 0..896
    const int wm = wid & 1;                 // 0: cos, 1: sin
    const int wn = wid >> 1;                // 0..3

    // cp.async per-thread pattern: 4 float4 per matrix per chunk
    uint32_t dsto[4];
    uint64_t so[4];
    #pragma unroll
    for (int r = 0; r < 4; r++) {
        int idx = tid + r * 256;            // 0..1023
        int row = idx >> 3;                 // 0..127
        int kg  = idx & 7;                  // 16B group
        dsto[r] = (uint32_t)(row * 128 + ((kg ^ (row & 7)) << 4));
        so[r]   = ((uint64_t)row * NFFT + (uint64_t)kg * 4) * 4;   // bytes
    }
    uint64_t gwc, gws, gBB;
    { const float* p = g_wc + (size_t)k0 * NFFT;
      asm("cvta.to.global.u64 %0, %1;" : "=l"(gwc) : "l"(p)); }
    { const float* p = g_ws + (size_t)k0 * NFFT;
      asm("cvta.to.global.u64 %0, %1;" : "=l"(gws) : "l"(p)); }
    { const float* p = g_B + (size_t)ct * NC * NFFT;
      asm("cvta.to.global.u64 %0, %1;" : "=l"(gBB) : "l"(p)); }

    float acc[8][4][4];
    #pragma unroll
    for (int a = 0; a < 8; a++)
        #pragma unroll
        for (int b = 0; b < 4; b++)
            #pragma unroll
            for (int c = 0; c < 4; c++) acc[a][b][c] = 0.f;

    // prologue: chunks 0,1
    #pragma unroll
    for (int i = 0; i < 2; i++) {
        uint32_t st = sb + i * STAGE_BYTES;
        uint64_t off = (uint64_t)i * KC * 4;
        #pragma unroll
        for (int r = 0; r < 4; r++) {
            cpa(st + dsto[r],                 gwc + off + so[r]);
            cpa(st + 16384 + dsto[r],         gws + off + so[r]);
            cpa(st + A_BYTES + dsto[r],       gBB + off + so[r]);
        }
        asm volatile("cp.async.commit_group;" ::: "memory");
    }

    int s = 0;
    for (int i = 0; i < NCHUNK; i++) {
        if (i < NCHUNK - 2)
            asm volatile("cp.async.wait_group 1;" ::: "memory");
        else
            asm volatile("cp.async.wait_group 0;" ::: "memory");
        __syncthreads();

        uint32_t st = sb + s * STAGE_BYTES;
        compute_chunk(st, acc, wm, wn, lane);

        if (i + 2 < NCHUNK) {
            int s2 = s + 2; if (s2 >= 3) s2 -= 3;
            uint32_t st2 = sb + s2 * STAGE_BYTES;
            uint64_t off = (uint64_t)(i + 2) * KC * 4;
            #pragma unroll
            for (int r = 0; r < 4; r++) {
                cpa(st2 + dsto[r],           gwc + off + so[r]);
                cpa(st2 + 16384 + dsto[r],   gws + off + so[r]);
                cpa(st2 + A_BYTES + dsto[r], gBB + off + so[r]);
            }
            asm volatile("cp.async.commit_group;" ::: "memory");
        }
        s++; if (s == 3) s = 0;
    }

    // ---- epilogue: direct stores + mirror (cos warps -> real, sin warps -> imag) ----
    const size_t TOT = (size_t)BATCH * NFFT * FRAMES;
    #pragma unroll
    for (int nt = 0; nt < 4; nt++) {
        int gc = ct * NC + wn * 32 + nt * 8 + (lane & 3) * 2;
        #pragma unroll
        for (int p = 0; p < 2; p++) {
            int g = gc + p;
            if (g >= NCOLS) continue;
            int b = g / FRAMES;
            int t = g - b * FRAMES;
            size_t cb = (size_t)b * ((size_t)NFFT * FRAMES) + t;
            #pragma unroll
            for (int mt = 0; mt < 8; mt++) {
                int k = k0 + mt * 16 + (lane >> 2);
                float v0 = acc[mt][nt][p];       // row k
                float v1 = acc[mt][nt][2 + p];   // row k+8
                if (wm == 0) {
                    out[cb + (size_t)k * FRAMES] = v0;
                    out[cb + (size_t)(k + 8) * FRAMES] = v1;
                    if (k >= 1) out[cb + (size_t)(NFFT - k) * FRAMES] = v0;
                    out[cb + (size_t)(NFFT - k - 8) * FRAMES] = v1;
                } else {
                    out[TOT + cb + (size_t)k * FRAMES] = -v0;
                    out[TOT + cb + (size_t)(k + 8) * FRAMES] = -v1;
                    if (k >= 1) out[TOT + cb + (size_t)(NFFT - k) * FRAMES] = v0;
                    out[TOT + cb + (size_t)(NFFT - k - 8) * FRAMES] = v1;
                }
            }
        }
    }
}

// ---------------- aux: k = 1024 row in exact fp32 ----------------
__global__ __launch_bounds__(256) void k1024_kernel(
    const float* __restrict__ x,
    const float* __restrict__ wsin,
    const float* __restrict__ wcos,
    float* __restrict__ out)
{
    int col = blockIdx.x * 8 + (threadIdx.x >> 5);
    if (col >= NCOLS) return;
    int lid = threadIdx.x & 31;
    int b = col / FRAMES;
    int t = col - b * FRAMES;
    const float* xb = x + (size_t)b * LENGTH;
    const float* wc = wcos + (size_t)1024 * NFFT;
    const float* ws = wsin + (size_t)1024 * NFFT;
    int base = t * HOP - (NFFT / 2);
    float ac = 0.f, as = 0.f;
    for (int n = lid; n < NFFT; n += 32) {
        int gi = base + n;
        if (gi < 0) gi = -gi;
        else if (gi >= LENGTH) gi = 2 * LENGTH - 2 - gi;
        float xv = xb[gi];
        ac = fmaf(wc[n], xv, ac);
        as = fmaf(ws[n], xv, as);
    }
    #pragma unroll
    for (int off = 16; off > 0; off >>= 1) {
        ac += __shfl_down_sync(0xFFFFFFFF, ac, off);
        as += __shfl_down_sync(0xFFFFFFFF, as, off);
    }
    if (lid == 0) {
        const size_t TOT = (size_t)BATCH * NFFT * FRAMES;
        size_t o = ((size_t)b * NFFT + 1024) * FRAMES + t;
        out[o] = ac;
        out[TOT + o] = -as;
    }
}

extern "C" void kernel_launch(void* const* d_in, const int* in_sizes, int n_in,
                              void* d_out, int out_size) {
    const float* x    = (const float*)d_in[0];
    const float* wsin = (const float*)d_in[1];
    const float* wcos = (const float*)d_in[2];
    float* out = (float*)d_out;

    cudaFuncSetAttribute(stft_mma, cudaFuncAttributeMaxDynamicSharedMemorySize, SMEM_TOTAL);

    round_w<<<(KBINS * NFFT / 4) / 256, 256>>>(wsin, wcos);   // 2048 blocks
    build_B<<<NCOLS_PAD, 256>>>(x);
    stft_mma<<<dim3(NCOLS_PAD / NC, KBINS / 128), 256, SMEM_TOTAL>>>(out);
    k1024_kernel<<<(NCOLS + 7) / 8, 256>>>(x, wsin, wcos, out);
}

// round 5
// speedup vs baseline: 5.9336x; 1.4592x over previous
#include <cuda_runtime.h>
#include <cstdint>

#define LENGTH   262144
#define NFFT     2048
#define HOP      512
#define BATCH    16
#define FRAMES   513
#define NCOLS    (BATCH * FRAMES)      // 8208
#define NPAD     8448                  // 33 * 256
#define KBINS    1024
#define KPAD     1088                  // 1025 live + pad to 34*32
#define KC       32
#define NCH      (KPAD / KC)           // 34
#define MT2      128                   // CTA rows (k bins)
#define NT2      256                   // CTA cols
#define A_BYTES  (MT2 * 128)           // 16384
#define B_BYTES  (NT2 * 128)           // 32768
#define STAGE_BYTES (A_BYTES + B_BYTES) // 49152
#define STAGES   4
#define SMEM_TOTAL (STAGES * STAGE_BYTES) // 196608

__device__ __align__(16) float g_wc2[KBINS * KPAD];   // 4.5 MB
__device__ __align__(16) float g_ws2[KBINS * KPAD];   // 4.5 MB
__device__ __align__(16) float g_Bp[NPAD * KPAD];     // 36.8 MB
__device__ __align__(16) float g_Bm[NPAD * KPAD];     // 36.8 MB

__device__ __forceinline__ uint32_t smem_u32(const void* p) {
    uint32_t a;
    asm("{ .reg .u64 t; cvta.to.shared.u64 t, %1; cvt.u32.u64 %0, t; }" : "=r"(a) : "l"(p));
    return a;
}
__device__ __forceinline__ float tf32r(float v) {
    uint32_t u;
    asm("cvt.rna.tf32.f32 %0, %1;" : "=r"(u) : "f"(v));
    return __uint_as_float(u);
}
__device__ __forceinline__ void cpa(uint32_t dst, uint64_t gsrc) {
    asm volatile("cp.async.cg.shared.global [%0], [%1], 16;" :: "r"(dst), "l"(gsrc) : "memory");
}
__device__ __forceinline__ void ldsm4(uint32_t* r, uint32_t a) {
    asm volatile("ldmatrix.sync.aligned.m8n8.x4.shared.b16 {%0,%1,%2,%3}, [%4];"
        : "=r"(r[0]), "=r"(r[1]), "=r"(r[2]), "=r"(r[3]) : "r"(a));
}
__device__ __forceinline__ void mma8(float* c, const uint32_t* a, const uint32_t* b) {
    asm volatile("mma.sync.aligned.m16n8k8.row.col.f32.tf32.tf32.f32 "
        "{%0,%1,%2,%3}, {%4,%5,%6,%7}, {%8,%9}, {%0,%1,%2,%3};"
        : "+f"(c[0]), "+f"(c[1]), "+f"(c[2]), "+f"(c[3])
        : "r"(a[0]), "r"(a[1]), "r"(a[2]), "r"(a[3]), "r"(b[0]), "r"(b[1]));
}

// ---- prep 1: fold/round W rows 0..1023, cols 0..1024 (+zero pad to 1088) ----
__global__ __launch_bounds__(256) void round_w2(
    const float* __restrict__ wsin, const float* __restrict__ wcos)
{
    int i = blockIdx.x * 256 + threadIdx.x;     // float4 idx over 1024*1088/4
    int row = i / (KPAD / 4);
    int j = (i - row * (KPAD / 4)) * 4;
    float4 c, s;
    float* cc = (float*)&c; float* ss = (float*)&s;
    #pragma unroll
    for (int e = 0; e < 4; e++) {
        int jj = j + e;
        if (jj <= 1024) {
            cc[e] = tf32r(wcos[(size_t)row * NFFT + jj]);
            ss[e] = tf32r(wsin[(size_t)row * NFFT + jj]);
        } else { cc[e] = 0.f; ss[e] = 0.f; }
    }
    *(float4*)(g_wc2 + (size_t)row * KPAD + j) = c;
    *(float4*)(g_ws2 + (size_t)row * KPAD + j) = s;
}

// ---- prep 2: folded frame matrices B_plus / B_minus with reflect pad ----
__device__ __forceinline__ float xrefl(const float* xb, int i) {
    if (i < 0) i = -i;
    else if (i >= LENGTH) i = 2 * LENGTH - 2 - i;
    return xb[i];
}
__global__ __launch_bounds__(256) void build_B2(const float* __restrict__ x)
{
    int col = blockIdx.x;                  // 0..NPAD-1
    int tid = threadIdx.x;
    float* bp = g_Bp + (size_t)col * KPAD;
    float* bm = g_Bm + (size_t)col * KPAD;
    if (col >= NCOLS) {
        for (int j = tid; j < KPAD; j += 256) { bp[j] = 0.f; bm[j] = 0.f; }
        return;
    }
    int b = col / FRAMES;
    int t = col - b * FRAMES;
    const float* xb = x + (size_t)b * LENGTH;
    int base = t * HOP - (NFFT / 2);
    for (int j = tid; j < KPAD; j += 256) {
        float vp, vm;
        if (j > 1024) { vp = 0.f; vm = 0.f; }
        else if (j == 0 || j == 1024) {
            float v = xrefl(xb, base + j);
            vp = tf32r(v); vm = tf32r(v);
        } else {
            float a = xrefl(xb, base + j);
            float c = xrefl(xb, base + NFFT - j);
            vp = tf32r(a + c);
            vm = tf32r(a - c);
        }
        bp[j] = vp; bm[j] = vm;
    }
}

// ---- main half-K GEMM: phase 0 = cos (real), phase 1 = sin (imag) ----
__global__ __launch_bounds__(256, 1) void stft_mma2(float* __restrict__ out)
{
    extern __shared__ __align__(128) char smem[];
    const uint32_t sb = smem_u32(smem);
    const int tid  = threadIdx.x;
    const int lane = tid & 31;
    const int wid  = tid >> 5;
    const int ct    = blockIdx.x;            // 0..32
    const int k0    = blockIdx.y * MT2;      // 0..896
    const int phase = blockIdx.z;            // 0 cos / 1 sin
    const int wm = wid & 1;                  // row half (64)
    const int wn = wid >> 1;                 // col quarter (64)

    // cp.async thread patterns
    uint32_t dstA[4]; uint64_t srcA[4];
    #pragma unroll
    for (int r = 0; r < 4; r++) {
        int idx = tid + r * 256;             // 0..1023
        int row = idx >> 3, kg = idx & 7;
        dstA[r] = (uint32_t)(row * 128 + ((kg ^ (row & 7)) << 4));
        srcA[r] = ((uint64_t)row * KPAD + (uint64_t)kg * 4) * 4;
    }
    uint32_t dstB[8]; uint64_t srcB[8];
    #pragma unroll
    for (int r = 0; r < 8; r++) {
        int idx = tid + r * 256;             // 0..2047
        int row = idx >> 3, kg = idx & 7;
        dstB[r] = (uint32_t)(row * 128 + ((kg ^ (row & 7)) << 4));
        srcB[r] = ((uint64_t)row * KPAD + (uint64_t)kg * 4) * 4;
    }
    uint64_t gA, gB;
    { const float* p = (phase ? g_ws2 : g_wc2) + (size_t)k0 * KPAD;
      asm("cvta.to.global.u64 %0, %1;" : "=l"(gA) : "l"(p)); }
    { const float* p = (phase ? g_Bm : g_Bp) + (size_t)ct * NT2 * KPAD;
      asm("cvta.to.global.u64 %0, %1;" : "=l"(gB) : "l"(p)); }

    float acc[4][8][4];
    #pragma unroll
    for (int a = 0; a < 4; a++)
        #pragma unroll
        for (int b = 0; b < 8; b++)
            #pragma unroll
            for (int c = 0; c < 4; c++) acc[a][b][c] = 0.f;

    // prologue: chunks 0..2
    #pragma unroll
    for (int i = 0; i < 3; i++) {
        uint32_t st = sb + i * STAGE_BYTES;
        uint64_t off = (uint64_t)i * KC * 4;
        #pragma unroll
        for (int r = 0; r < 4; r++) cpa(st + dstA[r], gA + off + srcA[r]);
        #pragma unroll
        for (int r = 0; r < 8; r++) cpa(st + A_BYTES + dstB[r], gB + off + srcB[r]);
        asm volatile("cp.async.commit_group;" ::: "memory");
    }

    const int arow = lane & 15;
    const int ahi  = (lane >> 4) & 1;
    const int bcol = wn * 64 + (lane & 7) + (((lane >> 4) & 1) << 3);
    const int bhi  = (lane >> 3) & 1;

    int s = 0;
    for (int i = 0; i < NCH; i++) {
        if (i < NCH - 2)
            asm volatile("cp.async.wait_group 2;" ::: "memory");
        else
            asm volatile("cp.async.wait_group 0;" ::: "memory");
        __syncthreads();

        const uint32_t st = sb + s * STAGE_BYTES;
        const uint32_t aBase = st + wm * (64 * 128);
        const uint32_t bBase = st + A_BYTES;
        #pragma unroll
        for (int ks = 0; ks < 4; ks++) {
            uint32_t bf[4][4];
            #pragma unroll
            for (int nt2 = 0; nt2 < 4; nt2++) {
                int col = bcol + nt2 * 16;
                int kg = ks * 2 + bhi;
                ldsm4(bf[nt2], bBase + col * 128 + ((kg ^ (col & 7)) << 4));
            }
            #pragma unroll
            for (int mt = 0; mt < 4; mt++) {
                int row = mt * 16 + arow;
                int kg = ks * 2 + ahi;
                uint32_t af[4];
                ldsm4(af, aBase + row * 128 + ((kg ^ (row & 7)) << 4));
                #pragma unroll
                for (int nt = 0; nt < 8; nt++)
                    mma8(acc[mt][nt], af, &bf[nt >> 1][(nt & 1) * 2]);
            }
        }

        if (i + 3 < NCH) {
            int s2 = s + 3; if (s2 >= STAGES) s2 -= STAGES;
            uint32_t st2 = sb + s2 * STAGE_BYTES;
            uint64_t off = (uint64_t)(i + 3) * KC * 4;
            #pragma unroll
            for (int r = 0; r < 4; r++) cpa(st2 + dstA[r], gA + off + srcA[r]);
            #pragma unroll
            for (int r = 0; r < 8; r++) cpa(st2 + A_BYTES + dstB[r], gB + off + srcB[r]);
            asm volatile("cp.async.commit_group;" ::: "memory");
        }
        s++; if (s == STAGES) s = 0;
    }

    // ---- epilogue: direct stores + mirror ----
    const size_t TOT = (size_t)BATCH * NFFT * FRAMES;
    #pragma unroll
    for (int nt = 0; nt < 8; nt++) {
        int gc = ct * NT2 + wn * 64 + nt * 8 + (lane & 3) * 2;
        #pragma unroll
        for (int p = 0; p < 2; p++) {
            int g = gc + p;
            if (g >= NCOLS) continue;
            int b = g / FRAMES;
            int t = g - b * FRAMES;
            size_t cb = (size_t)b * ((size_t)NFFT * FRAMES) + t;
            #pragma unroll
            for (int mt = 0; mt < 4; mt++) {
                int k = k0 + wm * 64 + mt * 16 + (lane >> 2);
                float v0 = acc[mt][nt][p];        // row k
                float v1 = acc[mt][nt][2 + p];    // row k+8
                if (phase == 0) {
                    out[cb + (size_t)k * FRAMES] = v0;
                    out[cb + (size_t)(k + 8) * FRAMES] = v1;
                    if (k >= 1) out[cb + (size_t)(NFFT - k) * FRAMES] = v0;
                    out[cb + (size_t)(NFFT - k - 8) * FRAMES] = v1;
                } else {
                    out[TOT + cb + (size_t)k * FRAMES] = -v0;
                    out[TOT + cb + (size_t)(k + 8) * FRAMES] = -v1;
                    if (k >= 1) out[TOT + cb + (size_t)(NFFT - k) * FRAMES] = v0;
                    out[TOT + cb + (size_t)(NFFT - k - 8) * FRAMES] = v1;
                }
            }
        }
    }
}

// ---- aux: k = 1024 row in exact fp32 ----
__global__ __launch_bounds__(256) void k1024_kernel(
    const float* __restrict__ x,
    const float* __restrict__ wsin,
    const float* __restrict__ wcos,
    float* __restrict__ out)
{
    int col = blockIdx.x * 8 + (threadIdx.x >> 5);
    if (col >= NCOLS) return;
    int lid = threadIdx.x & 31;
    int b = col / FRAMES;
    int t = col - b * FRAMES;
    const float* xb = x + (size_t)b * LENGTH;
    const float* wc = wcos + (size_t)1024 * NFFT;
    const float* ws = wsin + (size_t)1024 * NFFT;
    int base = t * HOP - (NFFT / 2);
    float ac = 0.f, as = 0.f;
    for (int n = lid; n < NFFT; n += 32) {
        int gi = base + n;
        if (gi < 0) gi = -gi;
        else if (gi >= LENGTH) gi = 2 * LENGTH - 2 - gi;
        float xv = xb[gi];
        ac = fmaf(wc[n], xv, ac);
        as = fmaf(ws[n], xv, as);
    }
    #pragma unroll
    for (int off = 16; off > 0; off >>= 1) {
        ac += __shfl_down_sync(0xFFFFFFFF, ac, off);
        as += __shfl_down_sync(0xFFFFFFFF, as, off);
    }
    if (lid == 0) {
        const size_t TOT = (size_t)BATCH * NFFT * FRAMES;
        size_t o = ((size_t)b * NFFT + 1024) * FRAMES + t;
        out[o] = ac;
        out[TOT + o] = -as;
    }
}

extern "C" void kernel_launch(void* const* d_in, const int* in_sizes, int n_in,
                              void* d_out, int out_size) {
    const float* x    = (const float*)d_in[0];
    const float* wsin = (const float*)d_in[1];
    const float* wcos = (const float*)d_in[2];
    float* out = (float*)d_out;

    cudaFuncSetAttribute(stft_mma2, cudaFuncAttributeMaxDynamicSharedMemorySize, SMEM_TOTAL);

    round_w2<<<(KBINS * KPAD / 4) / 256, 256>>>(wsin, wcos);   // 1088 blocks
    build_B2<<<NPAD, 256>>>(x);
    stft_mma2<<<dim3(NPAD / NT2, KBINS / MT2, 2), 256, SMEM_TOTAL>>>(out);
    k1024_kernel<<<(NCOLS + 7) / 8, 256>>>(x, wsin, wcos, out);
}

// round 6
// speedup vs baseline: 10.5764x; 1.7825x over previous
#include <cuda_runtime.h>
#include <cuda_fp16.h>
#include <cstdint>

#define LENGTH   262144
#define NFFT     2048
#define HOP      512
#define BATCH    16
#define FRAMES   513
#define NCOLS    (BATCH * FRAMES)      // 8208
#define NPAD     8448                  // 33 * 256
#define KBINS    1024                  // GEMM rows (k=1024 handled separately)
#define KROWS_W  1025                  // stored W rows (incl. k=1024)
#define KPAD     1088                  // 1025 live + pad
#define KC       64                    // halfs per chunk = 128 B/row
#define NCH      (KPAD / KC)           // 17
#define MT2      128
#define NT2      256
#define A_BYTES  (MT2 * 128)           // 16384
#define B_BYTES  (NT2 * 128)           // 32768
#define STAGE_BYTES (A_BYTES + B_BYTES)
#define STAGES   4
#define SMEM_TOTAL (STAGES * STAGE_BYTES) // 196608

__device__ __align__(16) __half g_wc2[KROWS_W * KPAD];   // 2.2 MB
__device__ __align__(16) __half g_ws2[KROWS_W * KPAD];
__device__ __align__(16) __half g_Bp[NPAD * KPAD];       // 18.4 MB
__device__ __align__(16) __half g_Bm[NPAD * KPAD];

__device__ __forceinline__ uint32_t smem_u32(const void* p) {
    uint32_t a;
    asm("{ .reg .u64 t; cvta.to.shared.u64 t, %1; cvt.u32.u64 %0, t; }" : "=r"(a) : "l"(p));
    return a;
}
__device__ __forceinline__ void cpa(uint32_t dst, uint64_t gsrc) {
    asm volatile("cp.async.cg.shared.global [%0], [%1], 16;" :: "r"(dst), "l"(gsrc) : "memory");
}
__device__ __forceinline__ void ldsm4(uint32_t* r, uint32_t a) {
    asm volatile("ldmatrix.sync.aligned.m8n8.x4.shared.b16 {%0,%1,%2,%3}, [%4];"
        : "=r"(r[0]), "=r"(r[1]), "=r"(r[2]), "=r"(r[3]) : "r"(a));
}
__device__ __forceinline__ void mma16(float* c, const uint32_t* a, const uint32_t* b) {
    asm volatile("mma.sync.aligned.m16n8k16.row.col.f32.f16.f16.f32 "
        "{%0,%1,%2,%3}, {%4,%5,%6,%7}, {%8,%9}, {%0,%1,%2,%3};"
        : "+f"(c[0]), "+f"(c[1]), "+f"(c[2]), "+f"(c[3])
        : "r"(a[0]), "r"(a[1]), "r"(a[2]), "r"(a[3]), "r"(b[0]), "r"(b[1]));
}

// ---- prep 1: fold W rows 0..1024 (cols 0..1024 live, pad to 1088) to fp16 ----
__global__ __launch_bounds__(256) void round_wh(
    const float* __restrict__ wsin, const float* __restrict__ wcos)
{
    int u = blockIdx.x * 256 + threadIdx.x;        // 16B unit = 8 halfs
    const int UPR = KPAD / 8;                      // 136 units per row
    int row = u / UPR;
    if (row >= KROWS_W) return;
    int j0 = (u - row * UPR) * 8;
    __half hc[8], hs[8];
    #pragma unroll
    for (int e = 0; e < 8; e++) {
        int j = j0 + e;
        if (j <= 1024) {
            hc[e] = __float2half_rn(wcos[(size_t)row * NFFT + j]);
            hs[e] = __float2half_rn(wsin[(size_t)row * NFFT + j]);
        } else { hc[e] = __float2half_rn(0.f); hs[e] = __float2half_rn(0.f); }
    }
    *(uint4*)(g_wc2 + (size_t)row * KPAD + j0) = *(uint4*)hc;
    *(uint4*)(g_ws2 + (size_t)row * KPAD + j0) = *(uint4*)hs;
}

// ---- prep 2: folded frame matrices (fp16) with reflect pad ----
__device__ __forceinline__ float xrefl(const float* xb, int i) {
    if (i < 0) i = -i;
    else if (i >= LENGTH) i = 2 * LENGTH - 2 - i;
    return xb[i];
}
__global__ __launch_bounds__(256) void build_Bh(const float* __restrict__ x)
{
    int col = blockIdx.x;
    int tid = threadIdx.x;
    __half* bp = g_Bp + (size_t)col * KPAD;
    __half* bm = g_Bm + (size_t)col * KPAD;
    if (col >= NCOLS) {
        for (int j = tid; j < KPAD; j += 256) {
            bp[j] = __float2half_rn(0.f); bm[j] = __float2half_rn(0.f);
        }
        return;
    }
    int b = col / FRAMES;
    int t = col - b * FRAMES;
    const float* xb = x + (size_t)b * LENGTH;
    int base = t * HOP - (NFFT / 2);
    for (int j = tid; j < KPAD; j += 256) {
        float vp, vm;
        if (j > 1024) { vp = 0.f; vm = 0.f; }
        else if (j == 0 || j == 1024) {
            float v = xrefl(xb, base + j);
            vp = v; vm = v;
        } else {
            float a = xrefl(xb, base + j);
            float c = xrefl(xb, base + NFFT - j);
            vp = a + c; vm = a - c;
        }
        bp[j] = __float2half_rn(vp);
        bm[j] = __float2half_rn(vm);
    }
}

// ---- main half-K fp16 GEMM: phase 0 = cos (real), 1 = sin (imag) ----
__global__ __launch_bounds__(256, 1) void stft_mma3(float* __restrict__ out)
{
    extern __shared__ __align__(128) char smem[];
    const uint32_t sb = smem_u32(smem);
    const int tid  = threadIdx.x;
    const int lane = tid & 31;
    const int wid  = tid >> 5;
    const int ct    = blockIdx.x;            // 0..32
    const int k0    = blockIdx.y * MT2;      // 0..896
    const int phase = blockIdx.z;
    const int wm = wid & 1;
    const int wn = wid >> 1;

    uint32_t dstA[4]; uint64_t srcA[4];
    #pragma unroll
    for (int r = 0; r < 4; r++) {
        int idx = tid + r * 256;
        int row = idx >> 3, kg = idx & 7;
        dstA[r] = (uint32_t)(row * 128 + ((kg ^ (row & 7)) << 4));
        srcA[r] = (uint64_t)row * (KPAD * 2) + (uint64_t)kg * 16;
    }
    uint32_t dstB[8]; uint64_t srcB[8];
    #pragma unroll
    for (int r = 0; r < 8; r++) {
        int idx = tid + r * 256;
        int row = idx >> 3, kg = idx & 7;
        dstB[r] = (uint32_t)(row * 128 + ((kg ^ (row & 7)) << 4));
        srcB[r] = (uint64_t)row * (KPAD * 2) + (uint64_t)kg * 16;
    }
    uint64_t gA, gB;
    { const __half* p = (phase ? g_ws2 : g_wc2) + (size_t)k0 * KPAD;
      asm("cvta.to.global.u64 %0, %1;" : "=l"(gA) : "l"(p)); }
    { const __half* p = (phase ? g_Bm : g_Bp) + (size_t)ct * NT2 * KPAD;
      asm("cvta.to.global.u64 %0, %1;" : "=l"(gB) : "l"(p)); }

    float acc[4][8][4];
    #pragma unroll
    for (int a = 0; a < 4; a++)
        #pragma unroll
        for (int b = 0; b < 8; b++)
            #pragma unroll
            for (int c = 0; c < 4; c++) acc[a][b][c] = 0.f;

    #pragma unroll
    for (int i = 0; i < 3; i++) {
        uint32_t st = sb + i * STAGE_BYTES;
        uint64_t off = (uint64_t)i * (KC * 2);
        #pragma unroll
        for (int r = 0; r < 4; r++) cpa(st + dstA[r], gA + off + srcA[r]);
        #pragma unroll
        for (int r = 0; r < 8; r++) cpa(st + A_BYTES + dstB[r], gB + off + srcB[r]);
        asm volatile("cp.async.commit_group;" ::: "memory");
    }

    const int arow = lane & 15;
    const int ahi  = (lane >> 4) & 1;
    const int bcol = wn * 64 + (lane & 7) + (((lane >> 4) & 1) << 3);
    const int bhi  = (lane >> 3) & 1;

    int s = 0;
    for (int i = 0; i < NCH; i++) {
        if (i < NCH - 2)
            asm volatile("cp.async.wait_group 2;" ::: "memory");
        else
            asm volatile("cp.async.wait_group 0;" ::: "memory");
        __syncthreads();

        const uint32_t st = sb + s * STAGE_BYTES;
        const uint32_t aBase = st + wm * (64 * 128);
        const uint32_t bBase = st + A_BYTES;
        #pragma unroll
        for (int ks = 0; ks < 4; ks++) {           // 4 k-steps of 16 halfs
            uint32_t bf[4][4];
            #pragma unroll
            for (int nt2 = 0; nt2 < 4; nt2++) {
                int col = bcol + nt2 * 16;
                int kg = ks * 2 + bhi;
                ldsm4(bf[nt2], bBase + col * 128 + ((kg ^ (col & 7)) << 4));
            }
            #pragma unroll
            for (int mt = 0; mt < 4; mt++) {
                int row = mt * 16 + arow;
                int kg = ks * 2 + ahi;
                uint32_t af[4];
                ldsm4(af, aBase + row * 128 + ((kg ^ (row & 7)) << 4));
                #pragma unroll
                for (int nt = 0; nt < 8; nt++)
                    mma16(acc[mt][nt], af, &bf[nt >> 1][(nt & 1) * 2]);
            }
        }

        if (i + 3 < NCH) {
            int s2 = s + 3; if (s2 >= STAGES) s2 -= STAGES;
            uint32_t st2 = sb + s2 * STAGE_BYTES;
            uint64_t off = (uint64_t)(i + 3) * (KC * 2);
            #pragma unroll
            for (int r = 0; r < 4; r++) cpa(st2 + dstA[r], gA + off + srcA[r]);
            #pragma unroll
            for (int r = 0; r < 8; r++) cpa(st2 + A_BYTES + dstB[r], gB + off + srcB[r]);
            asm volatile("cp.async.commit_group;" ::: "memory");
        }
        s++; if (s == STAGES) s = 0;
    }

    const size_t TOT = (size_t)BATCH * NFFT * FRAMES;
    #pragma unroll
    for (int nt = 0; nt < 8; nt++) {
        int gc = ct * NT2 + wn * 64 + nt * 8 + (lane & 3) * 2;
        #pragma unroll
        for (int p = 0; p < 2; p++) {
            int g = gc + p;
            if (g >= NCOLS) continue;
            int b = g / FRAMES;
            int t = g - b * FRAMES;
            size_t cb = (size_t)b * ((size_t)NFFT * FRAMES) + t;
            #pragma unroll
            for (int mt = 0; mt < 4; mt++) {
                int k = k0 + wm * 64 + mt * 16 + (lane >> 2);
                float v0 = acc[mt][nt][p];
                float v1 = acc[mt][nt][2 + p];
                if (phase == 0) {
                    out[cb + (size_t)k * FRAMES] = v0;
                    out[cb + (size_t)(k + 8) * FRAMES] = v1;
                    if (k >= 1) out[cb + (size_t)(NFFT - k) * FRAMES] = v0;
                    out[cb + (size_t)(NFFT - k - 8) * FRAMES] = v1;
                } else {
                    out[TOT + cb + (size_t)k * FRAMES] = -v0;
                    out[TOT + cb + (size_t)(k + 8) * FRAMES] = -v1;
                    if (k >= 1) out[TOT + cb + (size_t)(NFFT - k) * FRAMES] = v0;
                    out[TOT + cb + (size_t)(NFFT - k - 8) * FRAMES] = v1;
                }
            }
        }
    }
}

// ---- k = 1024 row: dot(W_row1024, B_plus) per column; imag = 0 ----
__global__ __launch_bounds__(256) void k1024h(float* __restrict__ out)
{
    int col = blockIdx.x * 8 + (threadIdx.x >> 5);
    if (col >= NCOLS) return;
    int lid = threadIdx.x & 31;
    const __half* w = g_wc2 + (size_t)1024 * KPAD;
    const __half* bp = g_Bp + (size_t)col * KPAD;
    float ac = 0.f;
    for (int j = lid; j <= 1024; j += 32)
        ac = fmaf(__half2float(w[j]), __half2float(bp[j]), ac);
    #pragma unroll
    for (int off = 16; off > 0; off >>= 1)
        ac += __shfl_down_sync(0xFFFFFFFF, ac, off);
    if (lid == 0) {
        const size_t TOT = (size_t)BATCH * NFFT * FRAMES;
        int b = col / FRAMES;
        int t = col - b * FRAMES;
        size_t o = ((size_t)b * NFFT + 1024) * FRAMES + t;
        out[o] = ac;
        out[TOT + o] = 0.f;
    }
}

extern "C" void kernel_launch(void* const* d_in, const int* in_sizes, int n_in,
                              void* d_out, int out_size) {
    const float* x    = (const float*)d_in[0];
    const float* wsin = (const float*)d_in[1];
    const float* wcos = (const float*)d_in[2];
    float* out = (float*)d_out;

    cudaFuncSetAttribute(stft_mma3, cudaFuncAttributeMaxDynamicSharedMemorySize, SMEM_TOTAL);

    int wunits = KROWS_W * (KPAD / 8);
    round_wh<<<(wunits + 255) / 256, 256>>>(wsin, wcos);
    build_Bh<<<NPAD, 256>>>(x);
    stft_mma3<<<dim3(NPAD / NT2, KBINS / MT2, 2), 256, SMEM_TOTAL>>>(out);
    k1024h<<<(NCOLS + 7) / 8, 256>>>(out);
}

// round 7
// speedup vs baseline: 12.1160x; 1.1456x over previous
#include <cuda_runtime.h>
#include <cuda_fp16.h>
#include <cstdint>

#define LENGTH   262144
#define NFFT     2048
#define HOP      512
#define BATCH    16
#define FRAMES   513
#define NCOLS    (BATCH * FRAMES)      // 8208
#define NPAD     8448                  // 33 * 256
#define KP2      576                   // 513 live + pad (9 chunks of 64)
#define KC       64                    // halfs per chunk = 128 B/row
#define NCH      (KP2 / KC)            // 9
#define MROWS    512                   // m rows per phase (k = 2m+par)
#define MT2      128
#define NT2      256
#define A_BYTES  (MT2 * 128)
#define B_BYTES  (NT2 * 128)
#define STAGE_BYTES (A_BYTES + B_BYTES)
#define STAGES   4
#define SMEM_TOTAL (STAGES * STAGE_BYTES) // 196608

// phase order: 0=even-cos(Pe), 1=odd-cos(Po), 2=even-sin(Me), 3=odd-sin(Mo)
__device__ __align__(16) __half g_W[4 * MROWS * KP2];   // 2.4 MB
__device__ __align__(16) __half g_B[4 * NPAD * KP2];    // 38.9 MB

__device__ __forceinline__ uint32_t smem_u32(const void* p) {
    uint32_t a;
    asm("{ .reg .u64 t; cvta.to.shared.u64 t, %1; cvt.u32.u64 %0, t; }" : "=r"(a) : "l"(p));
    return a;
}
__device__ __forceinline__ void cpa(uint32_t dst, uint64_t gsrc) {
    asm volatile("cp.async.cg.shared.global [%0], [%1], 16;" :: "r"(dst), "l"(gsrc) : "memory");
}
__device__ __forceinline__ void ldsm4(uint32_t* r, uint32_t a) {
    asm volatile("ldmatrix.sync.aligned.m8n8.x4.shared.b16 {%0,%1,%2,%3}, [%4];"
        : "=r"(r[0]), "=r"(r[1]), "=r"(r[2]), "=r"(r[3]) : "r"(a));
}
__device__ __forceinline__ void mma16(float* c, const uint32_t* a, const uint32_t* b) {
    asm volatile("mma.sync.aligned.m16n8k16.row.col.f32.f16.f16.f32 "
        "{%0,%1,%2,%3}, {%4,%5,%6,%7}, {%8,%9}, {%0,%1,%2,%3};"
        : "+f"(c[0]), "+f"(c[1]), "+f"(c[2]), "+f"(c[3])
        : "r"(a[0]), "r"(a[1]), "r"(a[2]), "r"(a[3]), "r"(b[0]), "r"(b[1]));
}

// ---- prep 1: build the 4 basis matrices (pure cos/sin, window lives in B) ----
__global__ __launch_bounds__(256) void build_W()
{
    int idx = blockIdx.x * 256 + threadIdx.x;       // over MROWS * KP2
    if (idx >= MROWS * KP2) return;
    int m = idx / KP2;
    int n = idx - m * KP2;
    float ce = 0.f, co = 0.f, se = 0.f, so = 0.f;
    if (n <= 512) {
        float ue = (float)(m * n) / 512.0f;              // exact
        float uo = (float)((2 * m + 1) * n) / 1024.0f;   // exact
        ce = cospif(ue); se = sinpif(ue);
        co = cospif(uo); so = sinpif(uo);
    }
    g_W[0 * MROWS * KP2 + idx] = __float2half_rn(ce);
    g_W[1 * MROWS * KP2 + idx] = __float2half_rn(co);
    g_W[2 * MROWS * KP2 + idx] = __float2half_rn(se);
    g_W[3 * MROWS * KP2 + idx] = __float2half_rn(so);
}

// ---- prep 2: doubly-folded, windowed frame matrices ----
__device__ __forceinline__ float xrefl(const float* xb, int i) {
    if (i < 0) i = -i;
    else if (i >= LENGTH) i = 2 * LENGTH - 2 - i;
    return xb[i];
}
__global__ __launch_bounds__(256) void build_B4(const float* __restrict__ x)
{
    int col = blockIdx.x;
    int tid = threadIdx.x;
    __half* pe = g_B + 0 * (size_t)NPAD * KP2 + (size_t)col * KP2;
    __half* po = g_B + 1 * (size_t)NPAD * KP2 + (size_t)col * KP2;
    __half* me = g_B + 2 * (size_t)NPAD * KP2 + (size_t)col * KP2;
    __half* mo = g_B + 3 * (size_t)NPAD * KP2 + (size_t)col * KP2;
    if (col >= NCOLS) {
        __half z = __float2half_rn(0.f);
        for (int j = tid; j < KP2; j += 256) { pe[j] = z; po[j] = z; me[j] = z; mo[j] = z; }
        return;
    }
    int b = col / FRAMES;
    int t = col - b * FRAMES;
    const float* xb = x + (size_t)b * LENGTH;
    int base = t * HOP - (NFFT / 2);
    for (int j = tid; j < KP2; j += 256) {
        float vpe = 0.f, vpo = 0.f, vme = 0.f, vmo = 0.f;
        if (j <= 512) {
            float winj = 0.5f - 0.5f * cospif((float)j / 1024.0f);
            float winp = 0.5f - 0.5f * cospif((float)(1024 - j) / 1024.0f);
            float xa = xrefl(xb, base + j);
            float xb2 = xrefl(xb, base + NFFT - j);
            float xc = xrefl(xb, base + 1024 - j);
            float xd = xrefl(xb, base + 1024 + j);
            float qa = winj * (xa + xb2);      // q[j]
            float qb = winp * (xc + xd);       // q[1024-j]
            float ma = winj * (xa - xb2);      // m[j]
            float mb = winp * (xc - xd);       // m[1024-j]
            float h = (j == 0 || j == 512) ? 0.5f : 1.0f;
            vpe = (qa + qb) * h;
            vpo = (qa - qb) * h;
            vme = (ma - mb) * h;
            vmo = (ma + mb) * h;
        }
        pe[j] = __float2half_rn(vpe);
        po[j] = __float2half_rn(vpo);
        me[j] = __float2half_rn(vme);
        mo[j] = __float2half_rn(vmo);
    }
}

// ---- main GEMM: 4 phases, M=512 each, K=576 ----
__global__ __launch_bounds__(256, 1) void stft_mma4(float* __restrict__ out)
{
    extern __shared__ __align__(128) char smem[];
    const uint32_t sb = smem_u32(smem);
    const int tid  = threadIdx.x;
    const int lane = tid & 31;
    const int wid  = tid >> 5;
    const int ct    = blockIdx.x;            // 0..32
    const int k0    = blockIdx.y * MT2;      // 0..384 (m rows)
    const int phase = blockIdx.z;            // 0..3
    const int wm = wid & 1;
    const int wn = wid >> 1;
    const int par    = phase & 1;
    const int is_sin = phase >> 1;

    uint32_t dstA[4]; uint64_t srcA[4];
    #pragma unroll
    for (int r = 0; r < 4; r++) {
        int idx = tid + r * 256;
        int row = idx >> 3, kg = idx & 7;
        dstA[r] = (uint32_t)(row * 128 + ((kg ^ (row & 7)) << 4));
        srcA[r] = (uint64_t)row * (KP2 * 2) + (uint64_t)kg * 16;
    }
    uint32_t dstB[8]; uint64_t srcB[8];
    #pragma unroll
    for (int r = 0; r < 8; r++) {
        int idx = tid + r * 256;
        int row = idx >> 3, kg = idx & 7;
        dstB[r] = (uint32_t)(row * 128 + ((kg ^ (row & 7)) << 4));
        srcB[r] = (uint64_t)row * (KP2 * 2) + (uint64_t)kg * 16;
    }
    uint64_t gA, gB;
    { const __half* p = g_W + (size_t)phase * MROWS * KP2 + (size_t)k0 * KP2;
      asm("cvta.to.global.u64 %0, %1;" : "=l"(gA) : "l"(p)); }
    { const __half* p = g_B + (size_t)phase * NPAD * KP2 + (size_t)ct * NT2 * KP2;
      asm("cvta.to.global.u64 %0, %1;" : "=l"(gB) : "l"(p)); }

    float acc[4][8][4];
    #pragma unroll
    for (int a = 0; a < 4; a++)
        #pragma unroll
        for (int b = 0; b < 8; b++)
            #pragma unroll
            for (int c = 0; c < 4; c++) acc[a][b][c] = 0.f;

    #pragma unroll
    for (int i = 0; i < 3; i++) {
        uint32_t st = sb + i * STAGE_BYTES;
        uint64_t off = (uint64_t)i * (KC * 2);
        #pragma unroll
        for (int r = 0; r < 4; r++) cpa(st + dstA[r], gA + off + srcA[r]);
        #pragma unroll
        for (int r = 0; r < 8; r++) cpa(st + A_BYTES + dstB[r], gB + off + srcB[r]);
        asm volatile("cp.async.commit_group;" ::: "memory");
    }

    const int arow = lane & 15;
    const int ahi  = (lane >> 4) & 1;
    const int bcol = wn * 64 + (lane & 7) + (((lane >> 4) & 1) << 3);
    const int bhi  = (lane >> 3) & 1;

    int s = 0;
    for (int i = 0; i < NCH; i++) {
        if (i < NCH - 2)
            asm volatile("cp.async.wait_group 2;" ::: "memory");
        else
            asm volatile("cp.async.wait_group 0;" ::: "memory");
        __syncthreads();

        const uint32_t st = sb + s * STAGE_BYTES;
        const uint32_t aBase = st + wm * (64 * 128);
        const uint32_t bBase = st + A_BYTES;
        #pragma unroll
        for (int ks = 0; ks < 4; ks++) {
            uint32_t bf[4][4];
            #pragma unroll
            for (int nt2 = 0; nt2 < 4; nt2++) {
                int col = bcol + nt2 * 16;
                int kg = ks * 2 + bhi;
                ldsm4(bf[nt2], bBase + col * 128 + ((kg ^ (col & 7)) << 4));
            }
            #pragma unroll
            for (int mt = 0; mt < 4; mt++) {
                int row = mt * 16 + arow;
                int kg = ks * 2 + ahi;
                uint32_t af[4];
                ldsm4(af, aBase + row * 128 + ((kg ^ (row & 7)) << 4));
                #pragma unroll
                for (int nt = 0; nt < 8; nt++)
                    mma16(acc[mt][nt], af, &bf[nt >> 1][(nt & 1) * 2]);
            }
        }

        if (i + 3 < NCH) {
            int s2 = s + 3; if (s2 >= STAGES) s2 -= STAGES;
            uint32_t st2 = sb + s2 * STAGE_BYTES;
            uint64_t off = (uint64_t)(i + 3) * (KC * 2);
            #pragma unroll
            for (int r = 0; r < 4; r++) cpa(st2 + dstA[r], gA + off + srcA[r]);
            #pragma unroll
            for (int r = 0; r < 8; r++) cpa(st2 + A_BYTES + dstB[r], gB + off + srcB[r]);
            asm volatile("cp.async.commit_group;" ::: "memory");
        }
        s++; if (s == STAGES) s = 0;
    }

    // ---- epilogue: k = 2m + par; real (cos) / -imag (sin); mirrors ----
    const size_t TOT = (size_t)BATCH * NFFT * FRAMES;
    #pragma unroll
    for (int nt = 0; nt < 8; nt++) {
        int gc = ct * NT2 + wn * 64 + nt * 8 + (lane & 3) * 2;
        #pragma unroll
        for (int p = 0; p < 2; p++) {
            int g = gc + p;
            if (g >= NCOLS) continue;
            int b = g / FRAMES;
            int t = g - b * FRAMES;
            size_t cb = (size_t)b * ((size_t)NFFT * FRAMES) + t;
            #pragma unroll
            for (int mt = 0; mt < 4; mt++) {
                int m = k0 + wm * 64 + mt * 16 + (lane >> 2);
                int k = 2 * m + par;          // 0..1023 ; +16 for second row
                float v0 = acc[mt][nt][p];
                float v1 = acc[mt][nt][2 + p];
                if (!is_sin) {
                    out[cb + (size_t)k * FRAMES] = v0;
                    out[cb + (size_t)(k + 16) * FRAMES] = v1;
                    if (k >= 1) out[cb + (size_t)(NFFT - k) * FRAMES] = v0;
                    out[cb + (size_t)(NFFT - k - 16) * FRAMES] = v1;
                } else {
                    out[TOT + cb + (size_t)k * FRAMES] = -v0;
                    out[TOT + cb + (size_t)(k + 16) * FRAMES] = -v1;
                    if (k >= 1) out[TOT + cb + (size_t)(NFFT - k) * FRAMES] = v0;
                    out[TOT + cb + (size_t)(NFFT - k - 16) * FRAMES] = v1;
                }
            }
        }
    }
}

// ---- k = 1024: real = sum_n Pe[n] * (-1)^n ; imag = 0 ----
__global__ __launch_bounds__(256) void k1024f(float* __restrict__ out)
{
    int col = blockIdx.x * 8 + (threadIdx.x >> 5);
    if (col >= NCOLS) return;
    int lid = threadIdx.x & 31;
    const __half* pe = g_B + (size_t)col * KP2;   // phase 0 = Pe
    float ac = 0.f;
    for (int j = lid; j <= 512; j += 32) {
        float v = __half2float(pe[j]);
        ac += (j & 1) ? -v : v;
    }
    #pragma unroll
    for (int off = 16; off > 0; off >>= 1)
        ac += __shfl_down_sync(0xFFFFFFFF, ac, off);
    if (lid == 0) {
        const size_t TOT = (size_t)BATCH * NFFT * FRAMES;
        int b = col / FRAMES;
        int t = col - b * FRAMES;
        size_t o = ((size_t)b * NFFT + 1024) * FRAMES + t;
        out[o] = ac;
        out[TOT + o] = 0.f;
    }
}

extern "C" void kernel_launch(void* const* d_in, const int* in_sizes, int n_in,
                              void* d_out, int out_size) {
    const float* x = (const float*)d_in[0];
    float* out = (float*)d_out;

    cudaFuncSetAttribute(stft_mma4, cudaFuncAttributeMaxDynamicSharedMemorySize, SMEM_TOTAL);

    build_W<<<(MROWS * KP2 + 255) / 256, 256>>>();
    build_B4<<<NPAD, 256>>>(x);
    stft_mma4<<<dim3(NPAD / NT2, MROWS / MT2, 4), 256, SMEM_TOTAL>>>(out);
    k1024f<<<(NCOLS + 7) / 8, 256>>>(out);
}

// round 8
// speedup vs baseline: 13.1365x; 1.0842x over previous
#include <cuda_runtime.h>
#include <cuda_fp16.h>
#include <cstdint>

#define LENGTH   262144
#define NFFT     2048
#define HOP      512
#define BATCH    16
#define FRAMES   513
#define NCOLS    (BATCH * FRAMES)      // 8208
#define NPAD     8448                  // 33 * 256
#define KP2      576                   // 513 live + pad (9 chunks of 64)
#define KC       64
#define NCH      (KP2 / KC)            // 9
#define MROWS    512
#define MT2      128
#define NT2      256
#define A_BYTES  (MT2 * 128)
#define B_BYTES  (NT2 * 128)
#define STAGE_BYTES (A_BYTES + B_BYTES)
#define STAGES   4
#define SMEM_TOTAL (STAGES * STAGE_BYTES) // 196608

// phase order: 0=even-cos(Pe), 1=odd-cos(Po), 2=even-sin(Me), 3=odd-sin(Mo)
__device__ __align__(16) __half g_W[4 * MROWS * KP2];   // 2.4 MB
__device__ __align__(16) __half g_B[4 * NPAD * KP2];    // 38.9 MB
__device__ __align__(16) float  g_win[520];             // Hann window, j = 0..512

__device__ __forceinline__ uint32_t smem_u32(const void* p) {
    uint32_t a;
    asm("{ .reg .u64 t; cvta.to.shared.u64 t, %1; cvt.u32.u64 %0, t; }" : "=r"(a) : "l"(p));
    return a;
}
__device__ __forceinline__ void cpa(uint32_t dst, uint64_t gsrc) {
    asm volatile("cp.async.cg.shared.global [%0], [%1], 16;" :: "r"(dst), "l"(gsrc) : "memory");
}
__device__ __forceinline__ void ldsm4(uint32_t* r, uint32_t a) {
    asm volatile("ldmatrix.sync.aligned.m8n8.x4.shared.b16 {%0,%1,%2,%3}, [%4];"
        : "=r"(r[0]), "=r"(r[1]), "=r"(r[2]), "=r"(r[3]) : "r"(a));
}
__device__ __forceinline__ void mma16(float* c, const uint32_t* a, const uint32_t* b) {
    asm volatile("mma.sync.aligned.m16n8k16.row.col.f32.f16.f16.f32 "
        "{%0,%1,%2,%3}, {%4,%5,%6,%7}, {%8,%9}, {%0,%1,%2,%3};"
        : "+f"(c[0]), "+f"(c[1]), "+f"(c[2]), "+f"(c[3])
        : "r"(a[0]), "r"(a[1]), "r"(a[2]), "r"(a[3]), "r"(b[0]), "r"(b[1]));
}

// ---- prep 1: basis matrices + window table ----
__global__ __launch_bounds__(256) void build_W()
{
    int idx = blockIdx.x * 256 + threadIdx.x;
    if (idx < 513)
        g_win[idx] = 0.5f - 0.5f * cospif((float)idx / 1024.0f);
    if (idx >= MROWS * KP2) return;
    int m = idx / KP2;
    int n = idx - m * KP2;
    float ce = 0.f, co = 0.f, se = 0.f, so = 0.f;
    if (n <= 512) {
        float ue = (float)(m * n) / 512.0f;
        float uo = (float)((2 * m + 1) * n) / 1024.0f;
        ce = cospif(ue); se = sinpif(ue);
        co = cospif(uo); so = sinpif(uo);
    }
    g_W[0 * MROWS * KP2 + idx] = __float2half_rn(ce);
    g_W[1 * MROWS * KP2 + idx] = __float2half_rn(co);
    g_W[2 * MROWS * KP2 + idx] = __float2half_rn(se);
    g_W[3 * MROWS * KP2 + idx] = __float2half_rn(so);
}

// ---- prep 2: folded windowed frames (no transcendentals) + fused k=1024 row ----
__device__ __forceinline__ float xrefl(const float* xb, int i) {
    if (i < 0) i = -i;
    else if (i >= LENGTH) i = 2 * LENGTH - 2 - i;
    return xb[i];
}
__global__ __launch_bounds__(256) void build_B4(const float* __restrict__ x,
                                                float* __restrict__ out)
{
    __shared__ float red[8];
    int col = blockIdx.x;
    int tid = threadIdx.x;
    __half* pe = g_B + 0 * (size_t)NPAD * KP2 + (size_t)col * KP2;
    __half* po = g_B + 1 * (size_t)NPAD * KP2 + (size_t)col * KP2;
    __half* me = g_B + 2 * (size_t)NPAD * KP2 + (size_t)col * KP2;
    __half* mo = g_B + 3 * (size_t)NPAD * KP2 + (size_t)col * KP2;
    if (col >= NCOLS) {
        __half z = __float2half_rn(0.f);
        for (int j = tid; j < KP2; j += 256) { pe[j] = z; po[j] = z; me[j] = z; mo[j] = z; }
        return;
    }
    int b = col / FRAMES;
    int t = col - b * FRAMES;
    const float* xb = x + (size_t)b * LENGTH;
    int base = t * HOP - (NFFT / 2);
    float alt = 0.f;                       // Σ (−1)^j vpe  -> real[k=1024]
    for (int j = tid; j < KP2; j += 256) {
        float vpe = 0.f, vpo = 0.f, vme = 0.f, vmo = 0.f;
        if (j <= 512) {
            float winj = g_win[j];
            float winp = 1.0f - winj;      // win(1024-j) = 1 - win(j)
            float xa  = xrefl(xb, base + j);
            float xb2 = xrefl(xb, base + NFFT - j);
            float xc  = xrefl(xb, base + 1024 - j);
            float xd  = xrefl(xb, base + 1024 + j);
            float qa = winj * (xa + xb2);
            float qb = winp * (xc + xd);
            float ma = winj * (xa - xb2);
            float mb = winp * (xc - xd);
            float h = (j == 0 || j == 512) ? 0.5f : 1.0f;
            vpe = (qa + qb) * h;
            vpo = (qa - qb) * h;
            vme = (ma - mb) * h;
            vmo = (ma + mb) * h;
            alt += (j & 1) ? -vpe : vpe;
        }
        pe[j] = __float2half_rn(vpe);
        po[j] = __float2half_rn(vpo);
        me[j] = __float2half_rn(vme);
        mo[j] = __float2half_rn(vmo);
    }
    // block-reduce alt -> out[k=1024]
    #pragma unroll
    for (int off = 16; off > 0; off >>= 1)
        alt += __shfl_down_sync(0xFFFFFFFF, alt, off);
    if ((tid & 31) == 0) red[tid >> 5] = alt;
    __syncthreads();
    if (tid == 0) {
        float s = 0.f;
        #pragma unroll
        for (int w = 0; w < 8; w++) s += red[w];
        const size_t TOT = (size_t)BATCH * NFFT * FRAMES;
        size_t o = ((size_t)b * NFFT + 1024) * FRAMES + t;
        out[o] = s;
        out[TOT + o] = 0.f;
    }
}

// ---- main GEMM: 4 phases, M=512 each, K=576 ----
__global__ __launch_bounds__(256, 1) void stft_mma4(float* __restrict__ out)
{
    extern __shared__ __align__(128) char smem[];
    const uint32_t sb = smem_u32(smem);
    const int tid  = threadIdx.x;
    const int lane = tid & 31;
    const int wid  = tid >> 5;
    const int ct    = blockIdx.x;
    const int k0    = blockIdx.y * MT2;
    const int phase = blockIdx.z;
    const int wm = wid & 1;
    const int wn = wid >> 1;
    const int par    = phase & 1;
    const int is_sin = phase >> 1;

    uint32_t dstA[4]; uint64_t srcA[4];
    #pragma unroll
    for (int r = 0; r < 4; r++) {
        int idx = tid + r * 256;
        int row = idx >> 3, kg = idx & 7;
        dstA[r] = (uint32_t)(row * 128 + ((kg ^ (row & 7)) << 4));
        srcA[r] = (uint64_t)row * (KP2 * 2) + (uint64_t)kg * 16;
    }
    uint32_t dstB[8]; uint64_t srcB[8];
    #pragma unroll
    for (int r = 0; r < 8; r++) {
        int idx = tid + r * 256;
        int row = idx >> 3, kg = idx & 7;
        dstB[r] = (uint32_t)(row * 128 + ((kg ^ (row & 7)) << 4));
        srcB[r] = (uint64_t)row * (KP2 * 2) + (uint64_t)kg * 16;
    }
    uint64_t gA, gB;
    { const __half* p = g_W + (size_t)phase * MROWS * KP2 + (size_t)k0 * KP2;
      asm("cvta.to.global.u64 %0, %1;" : "=l"(gA) : "l"(p)); }
    { const __half* p = g_B + (size_t)phase * NPAD * KP2 + (size_t)ct * NT2 * KP2;
      asm("cvta.to.global.u64 %0, %1;" : "=l"(gB) : "l"(p)); }

    float acc[4][8][4];
    #pragma unroll
    for (int a = 0; a < 4; a++)
        #pragma unroll
        for (int b = 0; b < 8; b++)
            #pragma unroll
            for (int c = 0; c < 4; c++) acc[a][b][c] = 0.f;

    #pragma unroll
    for (int i = 0; i < 3; i++) {
        uint32_t st = sb + i * STAGE_BYTES;
        uint64_t off = (uint64_t)i * (KC * 2);
        #pragma unroll
        for (int r = 0; r < 4; r++) cpa(st + dstA[r], gA + off + srcA[r]);
        #pragma unroll
        for (int r = 0; r < 8; r++) cpa(st + A_BYTES + dstB[r], gB + off + srcB[r]);
        asm volatile("cp.async.commit_group;" ::: "memory");
    }

    const int arow = lane & 15;
    const int ahi  = (lane >> 4) & 1;
    const int bcol = wn * 64 + (lane & 7) + (((lane >> 4) & 1) << 3);
    const int bhi  = (lane >> 3) & 1;

    int s = 0;
    for (int i = 0; i < NCH; i++) {
        if (i < NCH - 2)
            asm volatile("cp.async.wait_group 2;" ::: "memory");
        else
            asm volatile("cp.async.wait_group 0;" ::: "memory");
        __syncthreads();

        const uint32_t st = sb + s * STAGE_BYTES;
        const uint32_t aBase = st + wm * (64 * 128);
        const uint32_t bBase = st + A_BYTES;
        #pragma unroll
        for (int ks = 0; ks < 4; ks++) {
            uint32_t bf[4][4];
            #pragma unroll
            for (int nt2 = 0; nt2 < 4; nt2++) {
                int col = bcol + nt2 * 16;
                int kg = ks * 2 + bhi;
                ldsm4(bf[nt2], bBase + col * 128 + ((kg ^ (col & 7)) << 4));
            }
            #pragma unroll
            for (int mt = 0; mt < 4; mt++) {
                int row = mt * 16 + arow;
                int kg = ks * 2 + ahi;
                uint32_t af[4];
                ldsm4(af, aBase + row * 128 + ((kg ^ (row & 7)) << 4));
                #pragma unroll
                for (int nt = 0; nt < 8; nt++)
                    mma16(acc[mt][nt], af, &bf[nt >> 1][(nt & 1) * 2]);
            }
        }

        if (i + 3 < NCH) {
            int s2 = s + 3; if (s2 >= STAGES) s2 -= STAGES;
            uint32_t st2 = sb + s2 * STAGE_BYTES;
            uint64_t off = (uint64_t)(i + 3) * (KC * 2);
            #pragma unroll
            for (int r = 0; r < 4; r++) cpa(st2 + dstA[r], gA + off + srcA[r]);
            #pragma unroll
            for (int r = 0; r < 8; r++) cpa(st2 + A_BYTES + dstB[r], gB + off + srcB[r]);
            asm volatile("cp.async.commit_group;" ::: "memory");
        }
        s++; if (s == STAGES) s = 0;
    }

    const size_t TOT = (size_t)BATCH * NFFT * FRAMES;
    #pragma unroll
    for (int nt = 0; nt < 8; nt++) {
        int gc = ct * NT2 + wn * 64 + nt * 8 + (lane & 3) * 2;
        #pragma unroll
        for (int p = 0; p < 2; p++) {
            int g = gc + p;
            if (g >= NCOLS) continue;
            int b = g / FRAMES;
            int t = g - b * FRAMES;
            size_t cb = (size_t)b * ((size_t)NFFT * FRAMES) + t;
            #pragma unroll
            for (int mt = 0; mt < 4; mt++) {
                int m = k0 + wm * 64 + mt * 16 + (lane >> 2);
                int k = 2 * m + par;
                float v0 = acc[mt][nt][p];
                float v1 = acc[mt][nt][2 + p];
                if (!is_sin) {
                    out[cb + (size_t)k * FRAMES] = v0;
                    out[cb + (size_t)(k + 16) * FRAMES] = v1;
                    if (k >= 1) out[cb + (size_t)(NFFT - k) * FRAMES] = v0;
                    out[cb + (size_t)(NFFT - k - 16) * FRAMES] = v1;
                } else {
                    out[TOT + cb + (size_t)k * FRAMES] = -v0;
                    out[TOT + cb + (size_t)(k + 16) * FRAMES] = -v1;
                    if (k >= 1) out[TOT + cb + (size_t)(NFFT - k) * FRAMES] = v0;
                    out[TOT + cb + (size_t)(NFFT - k - 16) * FRAMES] = v1;
                }
            }
        }
    }
}

extern "C" void kernel_launch(void* const* d_in, const int* in_sizes, int n_in,
                              void* d_out, int out_size) {
    const float* x = (const float*)d_in[0];
    float* out = (float*)d_out;

    cudaFuncSetAttribute(stft_mma4, cudaFuncAttributeMaxDynamicSharedMemorySize, SMEM_TOTAL);

    build_W<<<(MROWS * KP2 + 255) / 256, 256>>>();
    build_B4<<<NPAD, 256>>>(x, out);
    stft_mma4<<<dim3(NPAD / NT2, MROWS / MT2, 4), 256, SMEM_TOTAL>>>(out);
}